// round 16
// baseline (speedup 1.0000x reference)
#include <cuda_runtime.h>
#include <cuda_bf16.h>
#include <mma.h>
#include <math.h>

using namespace nvcuda;

#define T_TOK 524288
#define D_DIM 256
#define N_SEG 8192

__device__ __align__(16) __nv_bfloat16 g_mhi[N_SEG * D_DIM];
__device__ __align__(16) __nv_bfloat16 g_mlo[N_SEG * D_DIM];
__device__ __align__(16) __nv_bfloat16 g_Wh[D_DIM * D_DIM];
__device__ __align__(16) __nv_bfloat16 g_Wl[D_DIM * D_DIM];
__device__ __align__(16) float g_tg[N_SEG * D_DIM];   // RAW mean@W (pre-tanh)
__device__ int g_segstart[N_SEG + 1];

// ---------------------------------------------------------------------------
// Pass 0a: segment boundaries from sorted obj.
// ---------------------------------------------------------------------------
__global__ void k_bounds(const int* __restrict__ obj) {
    int t = blockIdx.x * blockDim.x + threadIdx.x;
    if (t >= T_TOK) return;
    if (t == 0) {
        int v0 = obj[0];
        for (int j = 0; j <= v0; ++j) g_segstart[j] = 0;
        int vl = obj[T_TOK - 1];
        for (int j = vl + 1; j <= N_SEG; ++j) g_segstart[j] = T_TOK;
    } else {
        int p = obj[t - 1], c = obj[t];
        for (int j = p + 1; j <= c; ++j) g_segstart[j] = t;
    }
}

// ---------------------------------------------------------------------------
// Pass 0b: split W into bf16 hi/lo once.
// ---------------------------------------------------------------------------
__global__ void k_splitW(const float* __restrict__ W) {
    int i = blockIdx.x * 256 + threadIdx.x;
    float v = W[i];
    __nv_bfloat16 h = __float2bfloat16(v);
    g_Wh[i] = h;
    g_Wl[i] = __float2bfloat16(v - __bfloat162float(h));
}

// ---------------------------------------------------------------------------
// Pass 1: per-segment mean -> bf16 hi/lo pair. One 512-thread block/segment.
// ---------------------------------------------------------------------------
__global__ void __launch_bounds__(512)
k_segmean(const float* __restrict__ emb) {
    int n = blockIdx.x, tid = threadIdx.x;
    __shared__ __align__(16) float red[8][256];
    int s = g_segstart[n], e = g_segstart[n + 1];

    int r = tid >> 6;
    int c4 = (tid & 63) * 4;
    const float4* base = (const float4*)emb + (c4 >> 2);

    float4 acc = make_float4(0.f, 0.f, 0.f, 0.f);
#pragma unroll 4
    for (int t = s + r; t < e; t += 8) {
        float4 v = __ldcs(base + (size_t)t * 64);
        acc.x += v.x; acc.y += v.y; acc.z += v.z; acc.w += v.w;
    }
    *(float4*)&red[r][c4] = acc;
    __syncthreads();

    if (tid < 256) {
        float sum = 0.f;
#pragma unroll
        for (int j = 0; j < 8; ++j) sum += red[j][tid];
        float mean = sum / fmaxf((float)(e - s), 1.f);
        __nv_bfloat16 h = __float2bfloat16(mean);
        g_mhi[(size_t)n * D_DIM + tid] = h;
        g_mlo[(size_t)n * D_DIM + tid] = __float2bfloat16(mean - __bfloat162float(h));
    }
}

// ---------------------------------------------------------------------------
// Pass 2: g_tg_raw = mean @ W via bf16 wmma (m16n16k16). Tile 64x64, K-slab
// 64 (4 rounds), grid 512 blocks for latency hiding. 8 warps: 4 in M x 2 in N,
// warp tile 16x32 (1x2 frags). No epilogue math (tanh lives in pass3).
// ---------------------------------------------------------------------------
#define GLD 72   // smem row stride in bf16 elements (64 + 8 pad)

__global__ void __launch_bounds__(256)
k_gemm() {
    __shared__ __align__(16) __nv_bfloat16 Ah[64][GLD], Al[64][GLD];
    __shared__ __align__(16) __nv_bfloat16 Bh[64][GLD], Bl[64][GLD];
    int tid = threadIdx.x;
    int w = tid >> 5;
    int wm = w >> 1, wn = w & 1;          // 4 warps in M (16 rows), 2 in N (32 cols)
    int bm = blockIdx.x * 64, bn = blockIdx.y * 64;

    wmma::fragment<wmma::accumulator, 16, 16, 16, float> acc[2];
    wmma::fill_fragment(acc[0], 0.f);
    wmma::fill_fragment(acc[1], 0.f);

    // staging: 64x64 bf16 = 512 uint4 chunks per array, 2 per thread
    int r0 = (tid * 2) >> 3,     c0 = ((tid * 2) & 7) * 8;
    int r1 = (tid * 2 + 1) >> 3, c1 = ((tid * 2 + 1) & 7) * 8;

    for (int k0 = 0; k0 < 256; k0 += 64) {
        *(uint4*)&Ah[r0][c0] = *(const uint4*)(g_mhi + (size_t)(bm + r0) * 256 + k0 + c0);
        *(uint4*)&Ah[r1][c1] = *(const uint4*)(g_mhi + (size_t)(bm + r1) * 256 + k0 + c1);
        *(uint4*)&Al[r0][c0] = *(const uint4*)(g_mlo + (size_t)(bm + r0) * 256 + k0 + c0);
        *(uint4*)&Al[r1][c1] = *(const uint4*)(g_mlo + (size_t)(bm + r1) * 256 + k0 + c1);
        *(uint4*)&Bh[r0][c0] = *(const uint4*)(g_Wh + (size_t)(k0 + r0) * 256 + bn + c0);
        *(uint4*)&Bh[r1][c1] = *(const uint4*)(g_Wh + (size_t)(k0 + r1) * 256 + bn + c1);
        *(uint4*)&Bl[r0][c0] = *(const uint4*)(g_Wl + (size_t)(k0 + r0) * 256 + bn + c0);
        *(uint4*)&Bl[r1][c1] = *(const uint4*)(g_Wl + (size_t)(k0 + r1) * 256 + bn + c1);
        __syncthreads();

#pragma unroll
        for (int ks = 0; ks < 4; ++ks) {
            wmma::fragment<wmma::matrix_a, 16, 16, 16, __nv_bfloat16, wmma::row_major> ahi, alo;
            wmma::fragment<wmma::matrix_b, 16, 16, 16, __nv_bfloat16, wmma::row_major> bhi[2], blo[2];
            wmma::load_matrix_sync(ahi, &Ah[wm * 16][ks * 16], GLD);
            wmma::load_matrix_sync(alo, &Al[wm * 16][ks * 16], GLD);
#pragma unroll
            for (int j = 0; j < 2; ++j) {
                wmma::load_matrix_sync(bhi[j], &Bh[ks * 16][wn * 32 + j * 16], GLD);
                wmma::load_matrix_sync(blo[j], &Bl[ks * 16][wn * 32 + j * 16], GLD);
            }
#pragma unroll
            for (int j = 0; j < 2; ++j) {
                wmma::mma_sync(acc[j], ahi, blo[j], acc[j]);
                wmma::mma_sync(acc[j], alo, bhi[j], acc[j]);
                wmma::mma_sync(acc[j], ahi, bhi[j], acc[j]);
            }
        }
        __syncthreads();
    }

#pragma unroll
    for (int j = 0; j < 2; ++j) {
        int row = bm + wm * 16;
        int col = bn + wn * 32 + j * 16;
        wmma::store_matrix_sync(g_tg + (size_t)row * 256 + col, acc[j],
                                256, wmma::mem_row_major);
    }
}

// ---------------------------------------------------------------------------
// Pass 3 (fused): tanh(tg_raw) at block start (MUFU hidden under DRAM
// streaming), then scores + weighted segment sum + broadcast.
// ---------------------------------------------------------------------------
__global__ void __launch_bounds__(256, 6)
k_score_rep_bcast(const float* __restrict__ emb, float* __restrict__ out) {
    int n = blockIdx.x, tid = threadIdx.x;
    __shared__ __align__(16) float stg[256];
    __shared__ __align__(16) float redw[8][256];
    __shared__ __align__(16) float srep[256];
    int s = g_segstart[n], e = g_segstart[n + 1];
    stg[tid] = tanhf(g_tg[(size_t)n * 256 + tid]);
    __syncthreads();
    int lane = tid & 31, w = tid >> 5;

    float4 tga = *(const float4*)&stg[lane * 8];
    float4 tgb = *(const float4*)&stg[lane * 8 + 4];
    float4 accA = make_float4(0.f, 0.f, 0.f, 0.f);
    float4 accB = make_float4(0.f, 0.f, 0.f, 0.f);

    const float4* base = (const float4*)emb + lane * 2;

    int t = s + 2 * w;
    for (; t + 1 < e; t += 16) {
        float4 a0 = __ldcs(base + (size_t)(t + 0) * 64);
        float4 b0 = __ldcs(base + (size_t)(t + 0) * 64 + 1);
        float4 a1 = __ldcs(base + (size_t)(t + 1) * 64);
        float4 b1 = __ldcs(base + (size_t)(t + 1) * 64 + 1);
        float d0 = a0.x*tga.x + a0.y*tga.y + a0.z*tga.z + a0.w*tga.w
                 + b0.x*tgb.x + b0.y*tgb.y + b0.z*tgb.z + b0.w*tgb.w;
        float d1 = a1.x*tga.x + a1.y*tga.y + a1.z*tga.z + a1.w*tga.w
                 + b1.x*tgb.x + b1.y*tgb.y + b1.z*tgb.z + b1.w*tgb.w;
#pragma unroll
        for (int off = 16; off; off >>= 1) {
            d0 += __shfl_xor_sync(0xffffffffu, d0, off);
            d1 += __shfl_xor_sync(0xffffffffu, d1, off);
        }
        float s0 = 1.f / (1.f + __expf(-d0));
        float s1 = 1.f / (1.f + __expf(-d1));
        accA.x += a0.x*s0 + a1.x*s1;
        accA.y += a0.y*s0 + a1.y*s1;
        accA.z += a0.z*s0 + a1.z*s1;
        accA.w += a0.w*s0 + a1.w*s1;
        accB.x += b0.x*s0 + b1.x*s1;
        accB.y += b0.y*s0 + b1.y*s1;
        accB.z += b0.z*s0 + b1.z*s1;
        accB.w += b0.w*s0 + b1.w*s1;
    }
    if (t < e) {
        float4 a0 = __ldcs(base + (size_t)t * 64);
        float4 b0 = __ldcs(base + (size_t)t * 64 + 1);
        float d0 = a0.x*tga.x + a0.y*tga.y + a0.z*tga.z + a0.w*tga.w
                 + b0.x*tgb.x + b0.y*tgb.y + b0.z*tgb.z + b0.w*tgb.w;
#pragma unroll
        for (int off = 16; off; off >>= 1)
            d0 += __shfl_xor_sync(0xffffffffu, d0, off);
        float s0 = 1.f / (1.f + __expf(-d0));
        accA.x += a0.x*s0; accA.y += a0.y*s0;
        accA.z += a0.z*s0; accA.w += a0.w*s0;
        accB.x += b0.x*s0; accB.y += b0.y*s0;
        accB.z += b0.z*s0; accB.w += b0.w*s0;
    }
    *(float4*)&redw[w][lane * 8]     = accA;
    *(float4*)&redw[w][lane * 8 + 4] = accB;
    __syncthreads();
    float sum = 0.f;
#pragma unroll
    for (int j = 0; j < 8; ++j) sum += redw[j][tid];
    srep[tid] = sum;
    __syncthreads();

    int c = tid & 63;
    int r = tid >> 6;
    float4 rv = *(const float4*)&srep[c * 4];
    float4* ob = (float4*)out + c;
    for (int tt = s + r; tt < e; tt += 4)
        __stcs(ob + (size_t)tt * 64, rv);
}

extern "C" void kernel_launch(void* const* d_in, const int* in_sizes, int n_in,
                              void* d_out, int out_size) {
    const float* emb = (const float*)d_in[0];
    const float* W   = (const float*)d_in[1];
    const int*   obj = (const int*)d_in[2];
    float*       out = (float*)d_out;

    k_bounds<<<(T_TOK + 255) / 256, 256>>>(obj);
    k_splitW<<<(D_DIM * D_DIM) / 256, 256>>>(W);
    k_segmean<<<N_SEG, 512>>>(emb);
    k_gemm<<<dim3(N_SEG / 64, D_DIM / 64), 256>>>();
    k_score_rep_bcast<<<N_SEG, 256>>>(emb, out);
}

// round 17
// speedup vs baseline: 1.0237x; 1.0237x over previous
#include <cuda_runtime.h>
#include <cuda_bf16.h>
#include <mma.h>
#include <math.h>

using namespace nvcuda;

#define T_TOK 524288
#define D_DIM 256
#define N_SEG 8192

__device__ __align__(16) float g_mean[N_SEG * D_DIM];
__device__ __align__(16) float g_tg[N_SEG * D_DIM];   // RAW mean@W (pre-tanh)
__device__ int g_segstart[N_SEG + 1];

// ---------------------------------------------------------------------------
// Pass 0: segment boundaries from sorted obj.
// ---------------------------------------------------------------------------
__global__ void k_bounds(const int* __restrict__ obj) {
    int t = blockIdx.x * blockDim.x + threadIdx.x;
    if (t >= T_TOK) return;
    if (t == 0) {
        int v0 = obj[0];
        for (int j = 0; j <= v0; ++j) g_segstart[j] = 0;
        int vl = obj[T_TOK - 1];
        for (int j = vl + 1; j <= N_SEG; ++j) g_segstart[j] = T_TOK;
    } else {
        int p = obj[t - 1], c = obj[t];
        for (int j = p + 1; j <= c; ++j) g_segstart[j] = t;
    }
}

// ---------------------------------------------------------------------------
// Pass 1: per-segment mean. One 512-thread block per segment.
// ---------------------------------------------------------------------------
__global__ void __launch_bounds__(512)
k_segmean(const float* __restrict__ emb) {
    int n = blockIdx.x, tid = threadIdx.x;
    __shared__ __align__(16) float red[8][256];
    int s = g_segstart[n], e = g_segstart[n + 1];

    int r = tid >> 6;
    int c4 = (tid & 63) * 4;
    const float4* base = (const float4*)emb + (c4 >> 2);

    float4 acc = make_float4(0.f, 0.f, 0.f, 0.f);
#pragma unroll 4
    for (int t = s + r; t < e; t += 8) {
        float4 v = __ldcs(base + (size_t)t * 64);
        acc.x += v.x; acc.y += v.y; acc.z += v.z; acc.w += v.w;
    }
    *(float4*)&red[r][c4] = acc;
    __syncthreads();

    if (tid < 256) {
        float sum = 0.f;
#pragma unroll
        for (int j = 0; j < 8; ++j) sum += red[j][tid];
        g_mean[(size_t)n * D_DIM + tid] = sum / fmaxf((float)(e - s), 1.f);
    }
}

// ---------------------------------------------------------------------------
// Pass 2: g_tg_raw = mean @ W via bf16 wmma (m16n16k16), 2-term split done at
// staging, 3 products. No epilogue math (tanh lives in pass3).
// Block 128x64, 8 warps (4 M x 2 N), warp tile 32x32 (2x2 frags).
// ---------------------------------------------------------------------------
#define A_LD 48
#define B_LD 80

__global__ void __launch_bounds__(256)
k_gemm(const float* __restrict__ W) {
    __shared__ __align__(16) __nv_bfloat16 Ah[128][A_LD], Al[128][A_LD];
    __shared__ __align__(16) __nv_bfloat16 Bh[32][B_LD],  Bl[32][B_LD];
    int tid = threadIdx.x;
    int w = tid >> 5;
    int wm = w >> 1, wn = w & 1;
    int bm = blockIdx.x * 128, bn = blockIdx.y * 64;

    wmma::fragment<wmma::accumulator, 16, 16, 16, float> acc[2][2];
#pragma unroll
    for (int i = 0; i < 2; ++i)
#pragma unroll
        for (int j = 0; j < 2; ++j)
            wmma::fill_fragment(acc[i][j], 0.f);

    for (int k0 = 0; k0 < 256; k0 += 32) {
        // Stage A slab 128x32 with hi/lo split (1024 float4, 4/thread)
#pragma unroll
        for (int q = 0; q < 4; ++q) {
            int f = tid + q * 256;
            int row = f >> 3, c4 = (f & 7) * 4;
            float4 v = *(const float4*)(g_mean + (size_t)(bm + row) * 256 + k0 + c4);
            __nv_bfloat16 hx = __float2bfloat16(v.x);
            __nv_bfloat16 hy = __float2bfloat16(v.y);
            __nv_bfloat16 hz = __float2bfloat16(v.z);
            __nv_bfloat16 hw = __float2bfloat16(v.w);
            Ah[row][c4+0] = hx; Al[row][c4+0] = __float2bfloat16(v.x - __bfloat162float(hx));
            Ah[row][c4+1] = hy; Al[row][c4+1] = __float2bfloat16(v.y - __bfloat162float(hy));
            Ah[row][c4+2] = hz; Al[row][c4+2] = __float2bfloat16(v.z - __bfloat162float(hz));
            Ah[row][c4+3] = hw; Al[row][c4+3] = __float2bfloat16(v.w - __bfloat162float(hw));
        }
        // Stage B slab 32x64 with hi/lo split (512 float4, 2/thread)
#pragma unroll
        for (int q = 0; q < 2; ++q) {
            int f = tid + q * 256;
            int row = f >> 4, c4 = (f & 15) * 4;
            float4 v = *(const float4*)(W + (size_t)(k0 + row) * 256 + bn + c4);
            __nv_bfloat16 hx = __float2bfloat16(v.x);
            __nv_bfloat16 hy = __float2bfloat16(v.y);
            __nv_bfloat16 hz = __float2bfloat16(v.z);
            __nv_bfloat16 hw = __float2bfloat16(v.w);
            Bh[row][c4+0] = hx; Bl[row][c4+0] = __float2bfloat16(v.x - __bfloat162float(hx));
            Bh[row][c4+1] = hy; Bl[row][c4+1] = __float2bfloat16(v.y - __bfloat162float(hy));
            Bh[row][c4+2] = hz; Bl[row][c4+2] = __float2bfloat16(v.z - __bfloat162float(hz));
            Bh[row][c4+3] = hw; Bl[row][c4+3] = __float2bfloat16(v.w - __bfloat162float(hw));
        }
        __syncthreads();

#pragma unroll
        for (int ks = 0; ks < 2; ++ks) {
            wmma::fragment<wmma::matrix_a, 16, 16, 16, __nv_bfloat16, wmma::row_major> ahi[2], alo[2];
            wmma::fragment<wmma::matrix_b, 16, 16, 16, __nv_bfloat16, wmma::row_major> bhi[2], blo[2];
#pragma unroll
            for (int i = 0; i < 2; ++i) {
                wmma::load_matrix_sync(ahi[i], &Ah[wm * 32 + i * 16][ks * 16], A_LD);
                wmma::load_matrix_sync(alo[i], &Al[wm * 32 + i * 16][ks * 16], A_LD);
            }
#pragma unroll
            for (int j = 0; j < 2; ++j) {
                wmma::load_matrix_sync(bhi[j], &Bh[ks * 16][wn * 32 + j * 16], B_LD);
                wmma::load_matrix_sync(blo[j], &Bl[ks * 16][wn * 32 + j * 16], B_LD);
            }
#pragma unroll
            for (int i = 0; i < 2; ++i)
#pragma unroll
                for (int j = 0; j < 2; ++j) {
                    wmma::mma_sync(acc[i][j], ahi[i], blo[j], acc[i][j]);
                    wmma::mma_sync(acc[i][j], alo[i], bhi[j], acc[i][j]);
                    wmma::mma_sync(acc[i][j], ahi[i], bhi[j], acc[i][j]);
                }
        }
        __syncthreads();
    }

#pragma unroll
    for (int i = 0; i < 2; ++i)
#pragma unroll
        for (int j = 0; j < 2; ++j) {
            int row = bm + wm * 32 + i * 16;
            int col = bn + wn * 32 + j * 16;
            wmma::store_matrix_sync(g_tg + (size_t)row * 256 + col, acc[i][j],
                                    256, wmma::mem_row_major);
        }
}

// ---------------------------------------------------------------------------
// Pass 3 (fused): tanh(tg_raw) at block start (MUFU hidden under streaming),
// then scores + weighted segment sum + broadcast.
// ---------------------------------------------------------------------------
__global__ void __launch_bounds__(256, 6)
k_score_rep_bcast(const float* __restrict__ emb, float* __restrict__ out) {
    int n = blockIdx.x, tid = threadIdx.x;
    __shared__ __align__(16) float stg[256];
    __shared__ __align__(16) float redw[8][256];
    __shared__ __align__(16) float srep[256];
    int s = g_segstart[n], e = g_segstart[n + 1];
    stg[tid] = tanhf(g_tg[(size_t)n * 256 + tid]);
    __syncthreads();
    int lane = tid & 31, w = tid >> 5;

    float4 tga = *(const float4*)&stg[lane * 8];
    float4 tgb = *(const float4*)&stg[lane * 8 + 4];
    float4 accA = make_float4(0.f, 0.f, 0.f, 0.f);
    float4 accB = make_float4(0.f, 0.f, 0.f, 0.f);

    const float4* base = (const float4*)emb + lane * 2;

    int t = s + 2 * w;
    for (; t + 1 < e; t += 16) {
        float4 a0 = __ldcs(base + (size_t)(t + 0) * 64);
        float4 b0 = __ldcs(base + (size_t)(t + 0) * 64 + 1);
        float4 a1 = __ldcs(base + (size_t)(t + 1) * 64);
        float4 b1 = __ldcs(base + (size_t)(t + 1) * 64 + 1);
        float d0 = a0.x*tga.x + a0.y*tga.y + a0.z*tga.z + a0.w*tga.w
                 + b0.x*tgb.x + b0.y*tgb.y + b0.z*tgb.z + b0.w*tgb.w;
        float d1 = a1.x*tga.x + a1.y*tga.y + a1.z*tga.z + a1.w*tga.w
                 + b1.x*tgb.x + b1.y*tgb.y + b1.z*tgb.z + b1.w*tgb.w;
#pragma unroll
        for (int off = 16; off; off >>= 1) {
            d0 += __shfl_xor_sync(0xffffffffu, d0, off);
            d1 += __shfl_xor_sync(0xffffffffu, d1, off);
        }
        float s0 = 1.f / (1.f + __expf(-d0));
        float s1 = 1.f / (1.f + __expf(-d1));
        accA.x += a0.x*s0 + a1.x*s1;
        accA.y += a0.y*s0 + a1.y*s1;
        accA.z += a0.z*s0 + a1.z*s1;
        accA.w += a0.w*s0 + a1.w*s1;
        accB.x += b0.x*s0 + b1.x*s1;
        accB.y += b0.y*s0 + b1.y*s1;
        accB.z += b0.z*s0 + b1.z*s1;
        accB.w += b0.w*s0 + b1.w*s1;
    }
    if (t < e) {
        float4 a0 = __ldcs(base + (size_t)t * 64);
        float4 b0 = __ldcs(base + (size_t)t * 64 + 1);
        float d0 = a0.x*tga.x + a0.y*tga.y + a0.z*tga.z + a0.w*tga.w
                 + b0.x*tgb.x + b0.y*tgb.y + b0.z*tgb.z + b0.w*tgb.w;
#pragma unroll
        for (int off = 16; off; off >>= 1)
            d0 += __shfl_xor_sync(0xffffffffu, d0, off);
        float s0 = 1.f / (1.f + __expf(-d0));
        accA.x += a0.x*s0; accA.y += a0.y*s0;
        accA.z += a0.z*s0; accA.w += a0.w*s0;
        accB.x += b0.x*s0; accB.y += b0.y*s0;
        accB.z += b0.z*s0; accB.w += b0.w*s0;
    }
    *(float4*)&redw[w][lane * 8]     = accA;
    *(float4*)&redw[w][lane * 8 + 4] = accB;
    __syncthreads();
    float sum = 0.f;
#pragma unroll
    for (int j = 0; j < 8; ++j) sum += redw[j][tid];
    srep[tid] = sum;
    __syncthreads();

    int c = tid & 63;
    int r = tid >> 6;
    float4 rv = *(const float4*)&srep[c * 4];
    float4* ob = (float4*)out + c;
    for (int tt = s + r; tt < e; tt += 4)
        __stcs(ob + (size_t)tt * 64, rv);
}

extern "C" void kernel_launch(void* const* d_in, const int* in_sizes, int n_in,
                              void* d_out, int out_size) {
    const float* emb = (const float*)d_in[0];
    const float* W   = (const float*)d_in[1];
    const int*   obj = (const int*)d_in[2];
    float*       out = (float*)d_out;

    k_bounds<<<(T_TOK + 255) / 256, 256>>>(obj);
    k_segmean<<<N_SEG, 512>>>(emb);
    k_gemm<<<dim3(N_SEG / 128, D_DIM / 64), 256>>>(W);
    k_score_rep_bcast<<<N_SEG, 256>>>(emb, out);
}